// round 1
// baseline (speedup 1.0000x reference)
#include <cuda_runtime.h>

// KroneckerLinear: out[n, i*8+j] = sum_{k,l} x[n, k*8+l] * f1[i,k] * f2[j,l] + bias[i*8+j]
// Factored per row as Y = f1 @ X @ f2^T with X = reshape(row, 8, 8).
//
// Tile of 128 rows staged through shared memory for fully-coalesced global
// traffic; each thread computes one row. Padded pitch (68 floats = 17 float4)
// gives conflict-free LDS.128/STS.128 in both the coalesced and per-row phases.

#define TILE_ROWS 128
#define THREADS   128
#define PITCH4    17          // float4 units per row in smem (68 floats)

__global__ __launch_bounds__(THREADS)
void kron_linear_kernel(const float* __restrict__ x,
                        const float* __restrict__ f1,
                        const float* __restrict__ f2,
                        const float* __restrict__ bias,
                        float* __restrict__ out,
                        int nrows)
{
    __shared__ float4 sx[TILE_ROWS * PITCH4];   // 34,816 B
    __shared__ float  sf1[64];
    __shared__ float  sf2[64];
    __shared__ float  sb[64];

    const int tid = threadIdx.x;
    if (tid < 64) {
        sf1[tid] = f1[tid];
        sf2[tid] = f2[tid];
        sb[tid]  = bias[tid];
    }

    const long long row0 = (long long)blockIdx.x * TILE_ROWS;
    const int rows_here = (int)min((long long)TILE_ROWS, (long long)nrows - row0);
    const float4* gx   = (const float4*)x   + row0 * 16;   // 16 float4 per row
    float4*       gout = (float4*)out       + row0 * 16;

    // ---- stage tile (coalesced) ----
    #pragma unroll
    for (int i = 0; i < 16; i++) {
        int f = tid + i * THREADS;          // linear float4 index in tile
        int r = f >> 4;
        if (r < rows_here)
            sx[r * PITCH4 + (f & 15)] = gx[f];
    }
    __syncthreads();

    // ---- compute: this thread owns row `tid` ----
    if (tid < rows_here) {
        float y[64];
        #pragma unroll
        for (int m = 0; m < 64; m++) y[m] = sb[m];

        const float4* xrow = &sx[tid * PITCH4];
        const float4* f2v  = (const float4*)sf2;

        #pragma unroll 1
        for (int k = 0; k < 8; k++) {
            float4 xa = xrow[k * 2];
            float4 xb = xrow[k * 2 + 1];

            // t_k[j] = dot(X[k,:], f2[j,:])
            float tk[8];
            #pragma unroll
            for (int j = 0; j < 8; j++) {
                float4 fa = f2v[j * 2];
                float4 fb = f2v[j * 2 + 1];
                tk[j] = xa.x * fa.x + xa.y * fa.y + xa.z * fa.z + xa.w * fa.w
                      + xb.x * fb.x + xb.y * fb.y + xb.z * fb.z + xb.w * fb.w;
            }

            // Y[i][j] += f1[i,k] * t_k[j]
            #pragma unroll
            for (int i = 0; i < 8; i++) {
                float a = sf1[i * 8 + k];
                #pragma unroll
                for (int j = 0; j < 8; j++)
                    y[i * 8 + j] += a * tk[j];
            }
        }

        // write result back into own row slot (no cross-thread hazard)
        float4* yrow = &sx[tid * PITCH4];
        #pragma unroll
        for (int c = 0; c < 16; c++)
            yrow[c] = make_float4(y[c * 4 + 0], y[c * 4 + 1],
                                  y[c * 4 + 2], y[c * 4 + 3]);
    }
    __syncthreads();

    // ---- store tile (coalesced) ----
    #pragma unroll
    for (int i = 0; i < 16; i++) {
        int f = tid + i * THREADS;
        int r = f >> 4;
        if (r < rows_here)
            gout[f] = sx[r * PITCH4 + (f & 15)];
    }
}

extern "C" void kernel_launch(void* const* d_in, const int* in_sizes, int n_in,
                              void* d_out, int out_size)
{
    const float* x    = (const float*)d_in[0];
    const float* f1   = (const float*)d_in[1];
    const float* f2   = (const float*)d_in[2];
    const float* bias = (const float*)d_in[3];
    float* out = (float*)d_out;

    int nrows = in_sizes[0] / 64;
    int grid = (nrows + TILE_ROWS - 1) / TILE_ROWS;
    kron_linear_kernel<<<grid, THREADS>>>(x, f1, f2, bias, out, nrows);
}